// round 8
// baseline (speedup 1.0000x reference)
#include <cuda_runtime.h>
#include <math.h>

#define C_DT    0.01f
#define C_STEPS 100
#define C_NOSC  50
#define C_NPER  50
#define C_LIM   1.0471975511965976f   /* pi/3 */
#define C_MGL2  4.905f                /* m*g*(l/2), I = 1 */
#define NBP     13                    /* producer blocks: 4 oscillators each (52, 2 padded) */

__device__ __align__(128) float g_tq[C_STEPS * 64];  // [step][group 0..51]; 52..63 stay 0
__device__ unsigned g_prog[16];                       // per-block progress; consumer resets

__global__ __launch_bounds__(128, 1)
void cpg_fused(const float* __restrict__ x,
               const float* __restrict__ fc1_w, const float* __restrict__ fc1_b,
               const float* __restrict__ fc2_w, const float* __restrict__ fc2_b,
               const float* __restrict__ fc3_w, const float* __restrict__ fc3_b,
               const float* __restrict__ fcd_w, const float* __restrict__ fcd_b,
               const float* __restrict__ fc4_w, const float* __restrict__ fc4_b,
               const float* __restrict__ enc,  const float* __restrict__ osc_bias,
               const float* __restrict__ dec,
               float* __restrict__ out)
{
    const int tid = threadIdx.x;
    const int bid = blockIdx.x;
    const float x0 = x[0], x1 = x[1];

    if (bid < NBP) {
        // ============================ PRODUCER ============================
        __shared__ float sh_h[128];
        __shared__ float sh_h2[128];
        __shared__ float sh_o[8];

        // warp0: per-neuron constants. 8 lanes/osc, 4 osc/warp, 7 neurons/lane.
        float e0[7], e1[7], bb[7], d0[7], d1[7], w4[7];
        if (tid < 32) {
            const int q   = tid >> 3;
            const int l8  = tid & 7;
            const int osc = bid * 4 + q;
            #pragma unroll
            for (int k = 0; k < 7; ++k) {
                int n = l8 + 8 * k;
                if (osc < C_NOSC && n < C_NPER) {
                    int idx = osc * C_NPER + n;
                    e0[k] = enc[idx * 2 + 0];
                    e1[k] = enc[idx * 2 + 1];
                    bb[k] = osc_bias[idx];
                    d0[k] = dec[osc * 2 * C_NPER + n];
                    d1[k] = dec[osc * 2 * C_NPER + C_NPER + n];
                    w4[k] = fc4_w[idx];
                } else {
                    e0[k] = e1[k] = bb[k] = d0[k] = d1[k] = w4[k] = 0.f;
                }
            }
        }

        // h = relu(fc1 x + b1)
        {
            float v = fmaf(fc1_w[tid * 2], x0, fmaf(fc1_w[tid * 2 + 1], x1, fc1_b[tid]));
            sh_h[tid] = fmaxf(v, 0.f);
        }
        __syncthreads();

        // h2 = relu(fc2 h + b2)
        {
            const float4* wr = (const float4*)(fc2_w + tid * 128);
            float a0 = 0.f, a1 = 0.f, a2 = 0.f, a3 = 0.f;
            #pragma unroll 8
            for (int j = 0; j < 32; ++j) {
                float4 w = wr[j];
                a0 = fmaf(w.x, sh_h[4 * j + 0], a0);
                a1 = fmaf(w.y, sh_h[4 * j + 1], a1);
                a2 = fmaf(w.z, sh_h[4 * j + 2], a2);
                a3 = fmaf(w.w, sh_h[4 * j + 3], a3);
            }
            sh_h2[tid] = fmaxf((a0 + a1) + (a2 + a3) + fc2_b[tid], 0.f);
        }
        __syncthreads();

        // warp1: this block's 8 fc3 rows -> o0 (guard row < 100)
        if (tid >= 32 && tid < 64) {
            const int r     = (tid - 32) >> 2;
            const int lane4 = tid & 3;
            const int row   = bid * 8 + r;
            float s = 0.f;
            if (row < 2 * C_NOSC) {
                const float* wr = fc3_w + row * 128 + lane4 * 32;
                const float* hv = sh_h2 + lane4 * 32;
                #pragma unroll 8
                for (int k = 0; k < 32; ++k) s = fmaf(wr[k], hv[k], s);
            }
            s += __shfl_down_sync(0xffffffffu, s, 2, 4);
            s += __shfl_down_sync(0xffffffffu, s, 1, 4);
            if (lane4 == 0) sh_o[r] = (row < 2 * C_NOSC) ? s + fc3_b[row] : 0.f;
        }
        __syncthreads();

        // warp0: 100-step recurrence; progress published every 4 steps.
        if (tid < 32) {
            const int q  = tid >> 3;
            const int l8 = tid & 7;
            float s0 = sh_o[2 * q];
            float s1 = sh_o[2 * q + 1];
            float* tq_slot = g_tq + bid * 4 + q;
            unsigned* prog = g_prog + bid;

            for (int s = 0; s < C_STEPS; ++s) {
                // split accumulation chains (k0-3 / k4-6) to shorten the FMA path
                float a0a = 0.f, a1a = 0.f, ata = 0.f;
                float a0b = 0.f, a1b = 0.f, atb = 0.f;
                #pragma unroll
                for (int k = 0; k < 4; ++k) {
                    float a = fmaxf(fmaf(e0[k], s0, fmaf(e1[k], s1, bb[k])), 0.f);
                    a0a = fmaf(d0[k], a, a0a);
                    a1a = fmaf(d1[k], a, a1a);
                    ata = fmaf(w4[k], a, ata);
                }
                #pragma unroll
                for (int k = 4; k < 7; ++k) {
                    float a = fmaxf(fmaf(e0[k], s0, fmaf(e1[k], s1, bb[k])), 0.f);
                    a0b = fmaf(d0[k], a, a0b);
                    a1b = fmaf(d1[k], a, a1b);
                    atb = fmaf(w4[k], a, atb);
                }
                float a0 = a0a + a0b, a1 = a1a + a1b, at = ata + atb;
                #pragma unroll
                for (int off = 1; off < 8; off <<= 1) {
                    a0 += __shfl_xor_sync(0xffffffffu, a0, off, 8);
                    a1 += __shfl_xor_sync(0xffffffffu, a1, off, 8);
                    at += __shfl_xor_sync(0xffffffffu, at, off, 8);
                }
                s0 = fmaf(C_DT, a0, s0);
                s1 = fmaf(C_DT, a1, s1);
                if (l8 == 0) tq_slot[s * 64] = at;          // plain STG
                if (((s & 3) == 3) && tid == 0) {
                    unsigned v = (unsigned)(s + 1);
                    asm volatile("st.release.gpu.global.u32 [%0], %1;"
                                 :: "l"(prog), "r"(v) : "memory");
                }
            }
        }
    } else {
        // ============================ CONSUMER ============================
        __shared__ float sh_h[128];
        __shared__ float sh_direct;
        __shared__ float sh_torque[C_STEPS];
        __shared__ volatile int sh_ready[C_STEPS];
        __shared__ float sh_l[2 * C_STEPS];

        if (tid < C_STEPS) sh_ready[tid] = 0;

        // h = relu(fc1 x + b1); warp0 computes direct
        {
            float v = fmaf(fc1_w[tid * 2], x0, fmaf(fc1_w[tid * 2 + 1], x1, fc1_b[tid]));
            sh_h[tid] = fmaxf(v, 0.f);
        }
        __syncthreads();
        if (tid < 32) {
            float s = 0.f;
            #pragma unroll
            for (int k = 0; k < 4; ++k)
                s = fmaf(fcd_w[tid + 32 * k], sh_h[tid + 32 * k], s);
            #pragma unroll
            for (int off = 16; off; off >>= 1)
                s += __shfl_down_sync(0xffffffffu, s, off);
            if (tid == 0) sh_direct = s + fcd_b[0] + fc4_b[0];
        }
        __syncthreads();
        const float direct = sh_direct;

        const int wid  = tid >> 5;
        const int lane = tid & 31;

        if (wid < 3) {
            // reduce warps: warp w handles steps t ≡ w (mod 3)
            for (int t = wid; t < C_STEPS; t += 3) {
                for (;;) {
                    unsigned p = 0x7fffffffu;
                    if (lane < NBP)
                        asm volatile("ld.acquire.gpu.global.u32 %0, [%1];"
                                     : "=r"(p) : "l"(g_prog + lane));
                    unsigned m = __reduce_min_sync(0xffffffffu, p);
                    if (m > (unsigned)t) break;
                    __nanosleep(96);
                }
                // 52 real partials + 12 zero-pad: blind-load 64 floats
                float2 v = ((const float2*)(g_tq + t * 64))[lane];
                float s = v.x + v.y;
                #pragma unroll
                for (int off = 16; off; off >>= 1)
                    s += __shfl_xor_sync(0xffffffffu, s, off);
                if (lane == 0) {
                    sh_torque[t] = s + direct;
                    __threadfence_block();
                    sh_ready[t] = 1;
                }
            }
        } else if (tid == 96) {
            // limb warp: trail the reduce warps step-by-step
            volatile float* vtq = sh_torque;
            float th = x0, om = 0.f;
            for (int t = 0; t < C_STEPS; ++t) {
                while (!sh_ready[t]) { }
                float torque = vtq[t];
                float th2 = fmaf(C_DT, om, th);
                float om2 = fmaf(C_DT, torque - C_MGL2 * __sinf(th), om);
                bool hit = (th2 > C_LIM) || (th2 < -C_LIM);
                th2 = fminf(fmaxf(th2, -C_LIM), C_LIM);
                om2 = hit ? 0.f : om2;
                sh_l[2 * t]     = th2;
                sh_l[2 * t + 1] = om2;
                th = th2; om = om2;
            }
        }
        __syncthreads();

        // reset progress for the next graph replay (producers are all done)
        if (tid < NBP) g_prog[tid] = 0;

        // race-free coalesced output: out[0..199]=l_states, out[200..299]=torques
        out[tid] = sh_l[tid];
        if (tid < 72)  out[128 + tid] = sh_l[128 + tid];
        if (tid < 100) out[200 + tid] = sh_torque[tid];
    }
}

extern "C" void kernel_launch(void* const* d_in, const int* in_sizes, int n_in,
                              void* d_out, int out_size) {
    const float* x        = (const float*)d_in[0];
    const float* fc1_w    = (const float*)d_in[1];
    const float* fc1_b    = (const float*)d_in[2];
    const float* fc2_w    = (const float*)d_in[3];
    const float* fc2_b    = (const float*)d_in[4];
    const float* fc3_w    = (const float*)d_in[5];
    const float* fc3_b    = (const float*)d_in[6];
    const float* fcd_w    = (const float*)d_in[7];
    const float* fcd_b    = (const float*)d_in[8];
    const float* fc4_w    = (const float*)d_in[9];
    const float* fc4_b    = (const float*)d_in[10];
    const float* enc      = (const float*)d_in[11];
    const float* osc_bias = (const float*)d_in[12];
    const float* dec      = (const float*)d_in[13];
    float* out = (float*)d_out;

    cpg_fused<<<NBP + 1, 128>>>(x, fc1_w, fc1_b, fc2_w, fc2_b, fc3_w, fc3_b,
                                fcd_w, fcd_b, fc4_w, fc4_b, enc, osc_bias, dec, out);
}

// round 9
// speedup vs baseline: 1.3608x; 1.3608x over previous
#include <cuda_runtime.h>
#include <math.h>

#define C_DT    0.01f
#define C_STEPS 100
#define C_CHUNK 25
#define C_NOSC  50
#define C_NPER  50
#define C_LIM   1.0471975511965976f   /* pi/3 */
#define C_MGL2  4.905f                /* m*g*(l/2), I = 1 */
#define NBP     13                    /* producer blocks: 4 oscillators each (52, 2 padded) */

__device__ __align__(128) float g_tq[C_STEPS * 64];  // [step][group 0..51]; 52..63 stay 0
__device__ unsigned g_chunk[4];                       // per-chunk done-count; consumer resets

__global__ __launch_bounds__(128, 1)
void cpg_fused(const float* __restrict__ x,
               const float* __restrict__ fc1_w, const float* __restrict__ fc1_b,
               const float* __restrict__ fc2_w, const float* __restrict__ fc2_b,
               const float* __restrict__ fc3_w, const float* __restrict__ fc3_b,
               const float* __restrict__ fcd_w, const float* __restrict__ fcd_b,
               const float* __restrict__ fc4_w, const float* __restrict__ fc4_b,
               const float* __restrict__ enc,  const float* __restrict__ osc_bias,
               const float* __restrict__ dec,
               float* __restrict__ out)
{
    const int tid = threadIdx.x;
    const int bid = blockIdx.x;
    const float x0 = x[0], x1 = x[1];

    if (bid < NBP) {
        // ============================ PRODUCER ============================
        __shared__ float sh_h[128];
        __shared__ float sh_h2[128];
        __shared__ float sh_o[8];

        // warp0: per-neuron constants. 8 lanes/osc, 4 osc/warp, 7 neurons/lane.
        float e0[7], e1[7], bb[7], d0[7], d1[7], w4[7];
        if (tid < 32) {
            const int q   = tid >> 3;
            const int l8  = tid & 7;
            const int osc = bid * 4 + q;
            #pragma unroll
            for (int k = 0; k < 7; ++k) {
                int n = l8 + 8 * k;
                if (osc < C_NOSC && n < C_NPER) {
                    int idx = osc * C_NPER + n;
                    e0[k] = enc[idx * 2 + 0];
                    e1[k] = enc[idx * 2 + 1];
                    bb[k] = osc_bias[idx];
                    d0[k] = dec[osc * 2 * C_NPER + n];
                    d1[k] = dec[osc * 2 * C_NPER + C_NPER + n];
                    w4[k] = fc4_w[idx];
                } else {
                    e0[k] = e1[k] = bb[k] = d0[k] = d1[k] = w4[k] = 0.f;
                }
            }
        }

        // h = relu(fc1 x + b1)
        {
            float v = fmaf(fc1_w[tid * 2], x0, fmaf(fc1_w[tid * 2 + 1], x1, fc1_b[tid]));
            sh_h[tid] = fmaxf(v, 0.f);
        }
        __syncthreads();

        // h2 = relu(fc2 h + b2): one row per thread, float4 loads
        {
            const float4* wr = (const float4*)(fc2_w + tid * 128);
            float a0 = 0.f, a1 = 0.f, a2 = 0.f, a3 = 0.f;
            #pragma unroll 8
            for (int j = 0; j < 32; ++j) {
                float4 w = wr[j];
                a0 = fmaf(w.x, sh_h[4 * j + 0], a0);
                a1 = fmaf(w.y, sh_h[4 * j + 1], a1);
                a2 = fmaf(w.z, sh_h[4 * j + 2], a2);
                a3 = fmaf(w.w, sh_h[4 * j + 3], a3);
            }
            sh_h2[tid] = fmaxf((a0 + a1) + (a2 + a3) + fc2_b[tid], 0.f);
        }
        __syncthreads();

        // warp1: this block's 8 fc3 rows -> o0 (guard row < 100)
        if (tid >= 32 && tid < 64) {
            const int r     = (tid - 32) >> 2;
            const int lane4 = tid & 3;
            const int row   = bid * 8 + r;
            float s = 0.f;
            if (row < 2 * C_NOSC) {
                const float* wr = fc3_w + row * 128 + lane4 * 32;
                const float* hv = sh_h2 + lane4 * 32;
                #pragma unroll 8
                for (int k = 0; k < 32; ++k) s = fmaf(wr[k], hv[k], s);
            }
            s += __shfl_down_sync(0xffffffffu, s, 2, 4);
            s += __shfl_down_sync(0xffffffffu, s, 1, 4);
            if (lane4 == 0) sh_o[r] = (row < 2 * C_NOSC) ? s + fc3_b[row] : 0.f;
        }
        __syncthreads();

        // warp0: 100-step recurrence in 4 chunks of 25; one release per chunk.
        if (tid < 32) {
            const int q  = tid >> 3;
            const int l8 = tid & 7;
            float s0 = sh_o[2 * q];
            float s1 = sh_o[2 * q + 1];
            float* tq_slot = g_tq + bid * 4 + q;

            for (int c = 0; c < 4; ++c) {
                for (int i = 0; i < C_CHUNK; ++i) {
                    const int s = c * C_CHUNK + i;
                    // split decode chains (k0-3 / k4-6) to shorten the FMA path
                    float a0a = 0.f, a1a = 0.f, ata = 0.f;
                    float a0b = 0.f, a1b = 0.f, atb = 0.f;
                    #pragma unroll
                    for (int k = 0; k < 4; ++k) {
                        float a = fmaxf(fmaf(e0[k], s0, fmaf(e1[k], s1, bb[k])), 0.f);
                        a0a = fmaf(d0[k], a, a0a);
                        a1a = fmaf(d1[k], a, a1a);
                        ata = fmaf(w4[k], a, ata);
                    }
                    #pragma unroll
                    for (int k = 4; k < 7; ++k) {
                        float a = fmaxf(fmaf(e0[k], s0, fmaf(e1[k], s1, bb[k])), 0.f);
                        a0b = fmaf(d0[k], a, a0b);
                        a1b = fmaf(d1[k], a, a1b);
                        atb = fmaf(w4[k], a, atb);
                    }
                    float a0 = a0a + a0b, a1 = a1a + a1b, at = ata + atb;
                    // recurrence-critical butterfly first
                    #pragma unroll
                    for (int off = 1; off < 8; off <<= 1) {
                        a0 += __shfl_xor_sync(0xffffffffu, a0, off, 8);
                        a1 += __shfl_xor_sync(0xffffffffu, a1, off, 8);
                    }
                    s0 = fmaf(C_DT, a0, s0);
                    s1 = fmaf(C_DT, a1, s1);
                    // torque butterfly + store: off the recurrence path
                    #pragma unroll
                    for (int off = 1; off < 8; off <<= 1)
                        at += __shfl_xor_sync(0xffffffffu, at, off, 8);
                    if (l8 == 0) tq_slot[s * 64] = at;
                }
                // publish chunk c: all lanes fence their stores, sync, one atomic
                __threadfence();
                __syncwarp();
                if (tid == 0) atomicAdd(&g_chunk[c], 1u);
            }
        }
    } else {
        // ============================ CONSUMER ============================
        __shared__ float sh_h[128];
        __shared__ float sh_direct;
        __shared__ float sh_torque[C_STEPS];
        __shared__ float sh_l[2 * C_STEPS];

        // h = relu(fc1 x + b1); warp0 computes direct (overlaps producers)
        {
            float v = fmaf(fc1_w[tid * 2], x0, fmaf(fc1_w[tid * 2 + 1], x1, fc1_b[tid]));
            sh_h[tid] = fmaxf(v, 0.f);
        }
        __syncthreads();
        if (tid < 32) {
            float s = 0.f;
            #pragma unroll
            for (int k = 0; k < 4; ++k)
                s = fmaf(fcd_w[tid + 32 * k], sh_h[tid + 32 * k], s);
            #pragma unroll
            for (int off = 16; off; off >>= 1)
                s += __shfl_down_sync(0xffffffffu, s, off);
            if (tid == 0) sh_direct = s + fcd_b[0] + fc4_b[0];
        }
        __syncthreads();
        const float direct = sh_direct;

        float th = x0, om = 0.f;   // tid 0's limb state, carried across chunks

        for (int c = 0; c < 4; ++c) {
            // single-thread, single-line, sleepy poll (R7-proven pattern)
            if (tid == 0) {
                unsigned v;
                const unsigned* cp = &g_chunk[c];
                do {
                    asm volatile("ld.acquire.gpu.global.u32 %0, [%1];" : "=r"(v) : "l"(cp));
                    if (v < NBP) __nanosleep(64);
                } while (v < NBP);
            }
            __syncthreads();

            // 25 threads: reduce this chunk's 52 partials per step (blind-load 52)
            if (tid < C_CHUNK) {
                const int t = c * C_CHUNK + tid;
                const float4* row = (const float4*)(g_tq + t * 64);
                float acc = 0.f;
                #pragma unroll
                for (int j = 0; j < 13; ++j) {
                    float4 v = row[j];
                    acc += (v.x + v.y) + (v.z + v.w);
                }
                sh_torque[t] = acc + direct;
            }
            __syncthreads();

            // tid 0: limb integration for this chunk
            if (tid == 0) {
                #pragma unroll
                for (int i = 0; i < C_CHUNK; ++i) {
                    const int t = c * C_CHUNK + i;
                    float torque = sh_torque[t];
                    float th2 = fmaf(C_DT, om, th);
                    float om2 = fmaf(C_DT, torque - C_MGL2 * __sinf(th), om);
                    bool hit = (th2 > C_LIM) || (th2 < -C_LIM);
                    th2 = fminf(fmaxf(th2, -C_LIM), C_LIM);
                    om2 = hit ? 0.f : om2;
                    sh_l[2 * t]     = th2;
                    sh_l[2 * t + 1] = om2;
                    th = th2; om = om2;
                }
            }
        }
        __syncthreads();

        // reset chunk counters for the next graph replay (all producers done)
        if (tid < 4) g_chunk[tid] = 0;

        // race-free coalesced output: out[0..199]=l_states, out[200..299]=torques
        out[tid] = sh_l[tid];
        if (tid < 72)  out[128 + tid] = sh_l[128 + tid];
        if (tid < 100) out[200 + tid] = sh_torque[tid];
    }
}

extern "C" void kernel_launch(void* const* d_in, const int* in_sizes, int n_in,
                              void* d_out, int out_size) {
    const float* x        = (const float*)d_in[0];
    const float* fc1_w    = (const float*)d_in[1];
    const float* fc1_b    = (const float*)d_in[2];
    const float* fc2_w    = (const float*)d_in[3];
    const float* fc2_b    = (const float*)d_in[4];
    const float* fc3_w    = (const float*)d_in[5];
    const float* fc3_b    = (const float*)d_in[6];
    const float* fcd_w    = (const float*)d_in[7];
    const float* fcd_b    = (const float*)d_in[8];
    const float* fc4_w    = (const float*)d_in[9];
    const float* fc4_b    = (const float*)d_in[10];
    const float* enc      = (const float*)d_in[11];
    const float* osc_bias = (const float*)d_in[12];
    const float* dec      = (const float*)d_in[13];
    float* out = (float*)d_out;

    cpg_fused<<<NBP + 1, 128>>>(x, fc1_w, fc1_b, fc2_w, fc2_b, fc3_w, fc3_b,
                                fcd_w, fcd_b, fc4_w, fc4_b, enc, osc_bias, dec, out);
}